// round 15
// baseline (speedup 1.0000x reference)
#include <cuda_runtime.h>
#include <cuda_fp16.h>
#include <cstdint>
#include <math.h>

// ============================================================================
// HebbianPlasticLayer on sm_103 (base target -> classic mma.sync path).
//   y_slow = x @ W^T + bias
//   s      = (x*x/(||x||+1e-8)) @ sigmoid(alpha)^T
//   out    = y_slow + eta * tanh(y_slow) * s
// B = DIN = DOUT = 4096.
//
// R15: overhead trim. Alpha-constancy detection moved into rownorm (stream
// serialization makes the flag visible to later prep kernels), so when alpha
// is elementwise-constant: prep_x skips g_xxh, prep_wa skips alpha entirely,
// GEMM2 CTAs exit, plastic term fused exactly (rank-1) into GEMM1 epilogue.
// General path (alpha non-constant) keeps the proven R13 dual-GEMM flow.
// GEMM mainloop: cp.async for stage s+2 issued before kk0 ldsm batch.
// ============================================================================

static constexpr int ND = 4096;
static constexpr int BM = 128, BN = 128, BK = 64;   // 64 fp16 = 128 B rows
static constexpr int STAGES = 3;
static constexpr int KTILES = ND / BK;              // 64
static constexpr int STAGE_BYTES = (BM + BN) * BK * 2;  // 32768
static constexpr int OFF_B = BM * BK * 2;               // 16384
static constexpr int SMEM_BYTES = STAGES * STAGE_BYTES; // 98304
static constexpr int NTILES = (ND / BM) * (ND / BN);    // 1024

// ---------------- scratch (static device globals; no runtime alloc) ---------
__device__ __half g_xh [(size_t)ND * ND];   // fp16(x)
__device__ __half g_xxh[(size_t)ND * ND];   // fp16(x*x*inv_norm)   (general path)
__device__ __half g_wh [(size_t)ND * ND];   // fp16(W)
__device__ __half g_ah [(size_t)ND * ND];   // fp16(sigmoid(alpha)) (general path)
__device__ float  g_yslow[(size_t)ND * ND];
__device__ float  g_inv[ND];
__device__ float  g_rowsum[ND];             // ||x||^2 / (||x|| + 1e-8) per row
__device__ int    g_flags[NTILES];          // y_slow tile-ready flags
__device__ int    g_mismatch;               // 0 -> alpha elementwise-constant
__device__ float  g_sigc;                   // sigmoid(alpha[0])

// ---------------- small helpers ---------------------------------------------
__device__ __forceinline__ uint32_t smem_u32_of(const void* p) {
    uint32_t a;
    asm("{ .reg .u64 t; cvta.to.shared.u64 t, %1; cvt.u32.u64 %0, t; }"
        : "=r"(a) : "l"(p));
    return a;
}

__device__ __forceinline__ void cp16(uint32_t dst, const void* src) {
    asm volatile("cp.async.cg.shared.global [%0], [%1], 16;" :: "r"(dst), "l"(src));
}

__device__ __forceinline__ void ldsm_x4(uint32_t r[4], uint32_t addr) {
    asm volatile("ldmatrix.sync.aligned.m8n8.x4.shared.b16 {%0,%1,%2,%3}, [%4];"
                 : "=r"(r[0]), "=r"(r[1]), "=r"(r[2]), "=r"(r[3]) : "r"(addr));
}

__device__ __forceinline__ void mma16816(float c[4], const uint32_t a[4],
                                         uint32_t b0, uint32_t b1) {
    asm volatile(
        "mma.sync.aligned.m16n8k16.row.col.f32.f16.f16.f32 "
        "{%0,%1,%2,%3}, {%4,%5,%6,%7}, {%8,%9}, {%0,%1,%2,%3};"
        : "+f"(c[0]), "+f"(c[1]), "+f"(c[2]), "+f"(c[3])
        : "r"(a[0]), "r"(a[1]), "r"(a[2]), "r"(a[3]), "r"(b0), "r"(b1));
}

// accurate cheap tanh: 1 - 2/(e^{2y}+1), MUFU ex2 + rcp (err ~1e-6)
__device__ __forceinline__ float fast_tanh(float y) {
    float e = __expf(2.0f * y);
    return 1.0f - __fdividef(2.0f, e + 1.0f);
}

// ---------------- prep kernels -----------------------------------------------
// rownorm + alpha-constancy scan. grid = ND blocks x 256 threads.
// Each block: row-sum of x[row,:] AND scans a 4096-element slice of alpha.
__global__ void rownorm_kernel(const float* __restrict__ x,
                               const float* __restrict__ alpha) {
    const int row = blockIdx.x;
    const float4* xr = (const float4*)(x + (size_t)row * ND);
    float s = 0.f;
    for (int i = threadIdx.x; i < ND / 4; i += blockDim.x) {
        float4 v = xr[i];
        s += v.x * v.x + v.y * v.y + v.z * v.z + v.w * v.w;
    }
    // alpha slice scan: block b covers float4 indices [b*1024, (b+1)*1024)
    const float aref = __ldg(&alpha[0]);
    const float4* ar = (const float4*)alpha + (size_t)row * (ND / 4);
    bool diff = false;
    for (int i = threadIdx.x; i < ND / 4; i += blockDim.x) {
        float4 a = ar[i];
        diff |= (a.x != aref) | (a.y != aref) | (a.z != aref) | (a.w != aref);
    }
    if (__syncthreads_or(diff)) {
        if (threadIdx.x == 0) atomicExch(&g_mismatch, 1);
    }
    if (row == 0 && threadIdx.x == 0)
        g_sigc = __fdividef(1.f, 1.f + __expf(-aref));

    for (int o = 16; o; o >>= 1) s += __shfl_down_sync(0xFFFFFFFFu, s, o);
    __shared__ float red[8];
    if ((threadIdx.x & 31) == 0) red[threadIdx.x >> 5] = s;
    __syncthreads();
    if (threadIdx.x < 8) {
        float t = red[threadIdx.x];
        for (int o = 4; o; o >>= 1) t += __shfl_down_sync(0xFFu, t, o);
        if (threadIdx.x == 0) {
            float inv = 1.f / (sqrtf(t) + 1e-8f);
            g_inv[row] = inv;
            g_rowsum[row] = t * inv;   // sum_j x_norm[b,j]*x[b,j], exact fp32
        }
    }
}

// 2 float4 per thread; produces xh always, xxh only on the general path
__global__ void prep_x_kernel(const float* __restrict__ x) {
    const size_t base = 2 * ((size_t)blockIdx.x * blockDim.x + threadIdx.x);
    const int need_xx = g_mismatch;        // set by rownorm (stream-serial)
    float4 v0 = ((const float4*)x)[base];
    float4 v1 = ((const float4*)x)[base + 1];
    const float inv0 = g_inv[base >> 10];
    const float inv1 = g_inv[(base + 1) >> 10];
#pragma unroll
    for (int j = 0; j < 2; j++) {
        float4 v = j ? v1 : v0;
        float inv = j ? inv1 : inv0;
        size_t i = base + j;
        ((__half2*)g_xh)[2 * i + 0]  = __floats2half2_rn(v.x, v.y);
        ((__half2*)g_xh)[2 * i + 1]  = __floats2half2_rn(v.z, v.w);
        if (need_xx) {
            ((__half2*)g_xxh)[2 * i + 0] = __floats2half2_rn(v.x * v.x * inv, v.y * v.y * inv);
            ((__half2*)g_xxh)[2 * i + 1] = __floats2half2_rn(v.z * v.z * inv, v.w * v.w * inv);
        }
    }
}

// W prep always; alpha read/sigmoid/ah write only on the general path
__global__ void prep_wa_kernel(const float* __restrict__ W,
                               const float* __restrict__ alpha) {
    const size_t base = 2 * ((size_t)blockIdx.x * blockDim.x + threadIdx.x);
    const int need_a = g_mismatch;         // set by rownorm (stream-serial)
    float4 w0 = ((const float4*)W)[base];
    float4 w1 = ((const float4*)W)[base + 1];
    ((__half2*)g_wh)[2 * base + 0] = __floats2half2_rn(w0.x, w0.y);
    ((__half2*)g_wh)[2 * base + 1] = __floats2half2_rn(w0.z, w0.w);
    ((__half2*)g_wh)[2 * base + 2] = __floats2half2_rn(w1.x, w1.y);
    ((__half2*)g_wh)[2 * base + 3] = __floats2half2_rn(w1.z, w1.w);
    if (need_a) {
        float4 a0 = ((const float4*)alpha)[base];
        float4 a1 = ((const float4*)alpha)[base + 1];
#pragma unroll
        for (int j = 0; j < 2; j++) {
            float4 a = j ? a1 : a0;
            size_t i = base + j;
            float s0 = __fdividef(1.f, 1.f + __expf(-a.x));
            float s1 = __fdividef(1.f, 1.f + __expf(-a.y));
            float s2 = __fdividef(1.f, 1.f + __expf(-a.z));
            float s3 = __fdividef(1.f, 1.f + __expf(-a.w));
            ((__half2*)g_ah)[2 * i + 0] = __floats2half2_rn(s0, s1);
            ((__half2*)g_ah)[2 * i + 1] = __floats2half2_rn(s2, s3);
        }
    }
}

// ---------------- GEMM -------------------------------------------------------
// load one BK stage of A (BM x BK) and B (BN x BK), SW128 swizzled; 128 threads
__device__ __forceinline__ void load_stage(uint32_t smem_u32, int buf,
                                           const char* gA, const char* gB,
                                           int ks, int tid)
{
    const uint32_t sb = smem_u32 + buf * STAGE_BYTES;
    const size_t kof = (size_t)ks * (BK * 2);        // bytes into K
#pragma unroll
    for (int i = 0; i < 8; i++) {                    // A: 1024 chunks of 16B
        int c = tid + (i << 7);
        int r = c >> 3, kc = (c & 7) << 4;
        uint32_t off = (uint32_t)(r << 7) + kc;
        uint32_t sw = off ^ ((off >> 3) & 0x70);
        cp16(sb + sw, gA + (size_t)r * (ND * 2) + kof + kc);
    }
#pragma unroll
    for (int i = 0; i < 8; i++) {                    // B: 1024 chunks of 16B
        int c = tid + (i << 7);
        int r = c >> 3, kc = (c & 7) << 4;
        uint32_t off = (uint32_t)(r << 7) + kc;
        uint32_t sw = off ^ ((off >> 3) & 0x70);
        cp16(sb + OFF_B + sw, gB + (size_t)r * (ND * 2) + kof + kc);
    }
}

__global__ void __launch_bounds__(128, 2)
gemm_both_kernel(const float* __restrict__ bias, const float* __restrict__ eta_ptr,
                 float* __restrict__ out)
{
    extern __shared__ char smem[];
    const uint32_t smem_u32 = smem_u32_of(smem);
    const int tid = threadIdx.x;
    const int lane = tid & 31;
    const int wid = tid >> 5;             // 4 warps
    const int warp_m = wid & 1;           // 2 x 64 rows
    const int warp_n = wid >> 1;          // 2 x 64 cols

    // which GEMM: first NTILES CTAs -> y_slow, rest -> plastic
    const int mode = (blockIdx.x >= NTILES) ? 1 : 0;
    const int bid = blockIdx.x - mode * NTILES;

    const int aconst = (g_mismatch == 0);   // alpha elementwise-constant?
    if (mode == 1 && aconst) return;        // GEMM2 not needed: rank-1 fast path

    // grouped rasterization: 8 M-tiles per group, N sweeps fastest
    const int num_n = ND / BN;            // 32
    const int GROUP = 8;
    const int group = bid / (GROUP * num_n);
    const int tile_m = group * GROUP + (bid % GROUP);
    const int tile_n = (bid % (GROUP * num_n)) / GROUP;
    const int tile_id = tile_m * num_n + tile_n;

    const char* gA = (const char*)(mode ? g_xxh : g_xh) + (size_t)tile_m * BM * (ND * 2);
    const char* gB = (const char*)(mode ? g_ah  : g_wh) + (size_t)tile_n * BN * (ND * 2);

    // per-thread ldmatrix address components
    uint32_t a_row[4], a_xor[4];
#pragma unroll
    for (int mt = 0; mt < 4; mt++) {
        int r = warp_m * 64 + mt * 16 + (lane & 15);
        a_row[mt] = (uint32_t)(r << 7);
        a_xor[mt] = (uint32_t)((r & 7) << 4);
    }
    const uint32_t a_half = (uint32_t)((lane >> 4) << 4);
    uint32_t b_row[4], b_xor[4];
#pragma unroll
    for (int p = 0; p < 4; p++) {
        int r = warp_n * 64 + p * 16 + ((lane >> 4) << 3) + (lane & 7);
        b_row[p] = (uint32_t)(r << 7);
        b_xor[p] = (uint32_t)((r & 7) << 4);
    }
    const uint32_t b_half = (uint32_t)(((lane >> 3) & 1) << 4);

    float c[4][8][4];
#pragma unroll
    for (int i = 0; i < 4; i++)
#pragma unroll
        for (int j = 0; j < 8; j++)
#pragma unroll
            for (int k = 0; k < 4; k++) c[i][j][k] = 0.f;

    // double-buffered operand fragments
    uint32_t af[2][4][4];
    uint32_t bf[2][8][2];

    load_stage(smem_u32, 0, gA, gB, 0, tid);
    asm volatile("cp.async.commit_group;" ::: "memory");
    load_stage(smem_u32, 1, gA, gB, 1, tid);
    asm volatile("cp.async.commit_group;" ::: "memory");

    int buf = 0;
    int cur = 0;
#pragma unroll 1
    for (int s = 0; s < KTILES; s++) {
        if (s < KTILES - 2) asm volatile("cp.async.wait_group 1;" ::: "memory");
        else                asm volatile("cp.async.wait_group 0;" ::: "memory");
        __syncthreads();

        const uint32_t sbA = smem_u32 + buf * STAGE_BYTES;
        const uint32_t sbB = sbA + OFF_B;

        // issue next stage's cp.async FIRST: LDGSTS issue overlaps the serial
        // kk0 ldsm dependency chain below (2 warps/SMSP can't hide it alone)
        if (s + 2 < KTILES) {
            int nbuf = buf + 2; if (nbuf >= STAGES) nbuf -= STAGES;
            load_stage(smem_u32, nbuf, gA, gB, s + 2, tid);
            asm volatile("cp.async.commit_group;" ::: "memory");
        }

        // fragments for kk = 0
        {
            const uint32_t kb = 0;
#pragma unroll
            for (int mt = 0; mt < 4; mt++)
                ldsm_x4(af[cur][mt], sbA + a_row[mt] + ((kb + a_half) ^ a_xor[mt]));
#pragma unroll
            for (int p = 0; p < 4; p++) {
                uint32_t r[4];
                ldsm_x4(r, sbB + b_row[p] + ((kb + b_half) ^ b_xor[p]));
                bf[cur][2 * p][0] = r[0]; bf[cur][2 * p][1] = r[1];
                bf[cur][2 * p + 1][0] = r[2]; bf[cur][2 * p + 1][1] = r[3];
            }
        }

#pragma unroll
        for (int kk = 0; kk < 4; kk++) {
            const int nxt = cur ^ 1;
            if (kk < 3) {
                const uint32_t kb = (uint32_t)((kk + 1) << 5);
#pragma unroll
                for (int mt = 0; mt < 4; mt++)
                    ldsm_x4(af[nxt][mt], sbA + a_row[mt] + ((kb + a_half) ^ a_xor[mt]));
#pragma unroll
                for (int p = 0; p < 4; p++) {
                    uint32_t r[4];
                    ldsm_x4(r, sbB + b_row[p] + ((kb + b_half) ^ b_xor[p]));
                    bf[nxt][2 * p][0] = r[0]; bf[nxt][2 * p][1] = r[1];
                    bf[nxt][2 * p + 1][0] = r[2]; bf[nxt][2 * p + 1][1] = r[3];
                }
            }
#pragma unroll
            for (int mt = 0; mt < 4; mt++)
#pragma unroll
                for (int nt = 0; nt < 8; nt++)
                    mma16816(c[mt][nt], af[cur][mt], bf[cur][nt][0], bf[cur][nt][1]);
            if (kk < 3) cur = nxt;
        }
        buf++; if (buf >= STAGES) buf = 0;
    }

    // ---------------- epilogue ----------------
    const int row0 = tile_m * BM + warp_m * 64 + (lane >> 2);
    const int col0 = tile_n * BN + warp_n * 64 + ((lane & 3) << 1);

    if (mode == 0) {
        if (aconst) {
            // rank-1 fast path: out = y + eta*tanh(y)*(sigc*rowsum[row]), exact fp32 s
            const float eta = *eta_ptr;
            const float sigc = g_sigc;
#pragma unroll
            for (int mt = 0; mt < 4; mt++) {
                const int r0 = row0 + mt * 16;
                const int r1 = r0 + 8;
                const float s0 = sigc * __ldg(&g_rowsum[r0]);
                const float s1 = sigc * __ldg(&g_rowsum[r1]);
#pragma unroll
                for (int nt = 0; nt < 8; nt++) {
                    const int col = col0 + nt * 8;
                    float b0 = __ldg(&bias[col]);
                    float b1 = __ldg(&bias[col + 1]);
                    float y00 = c[mt][nt][0] + b0, y01 = c[mt][nt][1] + b1;
                    float y10 = c[mt][nt][2] + b0, y11 = c[mt][nt][3] + b1;
                    float2 v0, v1;
                    v0.x = y00 + eta * fast_tanh(y00) * s0;
                    v0.y = y01 + eta * fast_tanh(y01) * s0;
                    v1.x = y10 + eta * fast_tanh(y10) * s1;
                    v1.y = y11 + eta * fast_tanh(y11) * s1;
                    *(float2*)&out[(size_t)r0 * ND + col] = v0;
                    *(float2*)&out[(size_t)r1 * ND + col] = v1;
                }
            }
        } else {
            // general path: write y_slow tile, then release its flag
#pragma unroll
            for (int mt = 0; mt < 4; mt++) {
#pragma unroll
                for (int nt = 0; nt < 8; nt++) {
                    const int col = col0 + nt * 8;
                    const int r0 = row0 + mt * 16;
                    const int r1 = r0 + 8;
                    float b0 = __ldg(&bias[col]);
                    float b1 = __ldg(&bias[col + 1]);
                    float2 v0 = make_float2(c[mt][nt][0] + b0, c[mt][nt][1] + b1);
                    float2 v1 = make_float2(c[mt][nt][2] + b0, c[mt][nt][3] + b1);
                    *(float2*)&g_yslow[(size_t)r0 * ND + col] = v0;
                    *(float2*)&g_yslow[(size_t)r1 * ND + col] = v1;
                }
            }
            __threadfence();
            __syncthreads();
            if (tid == 0) atomicExch(&g_flags[tile_id], 1);
        }
    } else {
        // general path GEMM2: wait for matching y_slow tile
        if (tid == 0) {
            while (atomicCAS(&g_flags[tile_id], 1, 1) == 0) { }
        }
        __syncthreads();
        __threadfence();
        const float eta = *eta_ptr;
#pragma unroll
        for (int mt = 0; mt < 4; mt++) {
#pragma unroll
            for (int nt = 0; nt < 8; nt++) {
                const int col = col0 + nt * 8;
                const int r0 = row0 + mt * 16;
                const int r1 = r0 + 8;
                float2 y0 = *(const float2*)&g_yslow[(size_t)r0 * ND + col];
                float2 y1 = *(const float2*)&g_yslow[(size_t)r1 * ND + col];
                float2 v0, v1;
                v0.x = y0.x + eta * fast_tanh(y0.x) * c[mt][nt][0];
                v0.y = y0.y + eta * fast_tanh(y0.y) * c[mt][nt][1];
                v1.x = y1.x + eta * fast_tanh(y1.x) * c[mt][nt][2];
                v1.y = y1.y + eta * fast_tanh(y1.y) * c[mt][nt][3];
                *(float2*)&out[(size_t)r0 * ND + col] = v0;
                *(float2*)&out[(size_t)r1 * ND + col] = v1;
            }
        }
    }
}

// ---------------- launch -----------------------------------------------------
extern "C" void kernel_launch(void* const* d_in, const int* in_sizes, int n_in,
                              void* d_out, int out_size)
{
    // metadata order: x, W, alpha, eta, bias — resolve defensively by size
    const float* big[3] = {nullptr, nullptr, nullptr};
    const float* eta = nullptr;
    const float* bias = nullptr;
    int nb = 0;
    for (int i = 0; i < n_in; i++) {
        if (in_sizes[i] == 1) eta = (const float*)d_in[i];
        else if (in_sizes[i] == ND) bias = (const float*)d_in[i];
        else if (nb < 3) big[nb++] = (const float*)d_in[i];
    }
    const float* x = big[0];
    const float* W = big[1];
    const float* alpha = big[2];
    float* out = (float*)d_out;

    cudaFuncSetAttribute(gemm_both_kernel, cudaFuncAttributeMaxDynamicSharedMemorySize,
                         SMEM_BYTES);

    // reset flags + mismatch (graph-capturable memsets)
    void* flags_ptr = nullptr;
    cudaGetSymbolAddress(&flags_ptr, g_flags);
    cudaMemsetAsync(flags_ptr, 0, NTILES * sizeof(int));
    void* mm_ptr = nullptr;
    cudaGetSymbolAddress(&mm_ptr, g_mismatch);
    cudaMemsetAsync(mm_ptr, 0, sizeof(int));

    rownorm_kernel<<<ND, 256>>>(x, alpha);               // also detects alpha const
    const int n8blocks = (ND * (ND / 4)) / (256 * 2);    // 8192
    prep_x_kernel<<<n8blocks, 256>>>(x);
    prep_wa_kernel<<<n8blocks, 256>>>(W, alpha);

    gemm_both_kernel<<<2 * NTILES, 128, SMEM_BYTES>>>(bias, eta, out);
}

// round 16
// speedup vs baseline: 1.0512x; 1.0512x over previous
#include <cuda_runtime.h>
#include <cuda_fp16.h>
#include <cstdint>
#include <math.h>

// ============================================================================
// HebbianPlasticLayer on sm_103 (base target -> classic mma.sync path).
//   y_slow = x @ W^T + bias
//   s      = (x*x/(||x||+1e-8)) @ sigmoid(alpha)^T
//   out    = y_slow + eta * tanh(y_slow) * s
// B = DIN = DOUT = 4096.
//
// R16: recompose the two R15 sub-experiments by their measured outcomes:
//  - KEEP trimmed prep (alpha-constancy scan inside rownorm; fast path skips
//    g_xxh / g_ah traffic entirely)            [saved ~15us]
//  - REVERT mainloop reorder to R14 ordering (kk0 ldsm fragments first, then
//    issue stage s+2 cp.async)                 [reorder cost ~15us]
// Fast path (alpha elementwise-constant): GEMM2 vanishes, plastic term fused
// exactly (rank-1, fp32) into GEMM1 epilogue. General path: R13 dual-GEMM.
// ============================================================================

static constexpr int ND = 4096;
static constexpr int BM = 128, BN = 128, BK = 64;   // 64 fp16 = 128 B rows
static constexpr int STAGES = 3;
static constexpr int KTILES = ND / BK;              // 64
static constexpr int STAGE_BYTES = (BM + BN) * BK * 2;  // 32768
static constexpr int OFF_B = BM * BK * 2;               // 16384
static constexpr int SMEM_BYTES = STAGES * STAGE_BYTES; // 98304
static constexpr int NTILES = (ND / BM) * (ND / BN);    // 1024

// ---------------- scratch (static device globals; no runtime alloc) ---------
__device__ __half g_xh [(size_t)ND * ND];   // fp16(x)
__device__ __half g_xxh[(size_t)ND * ND];   // fp16(x*x*inv_norm)   (general path)
__device__ __half g_wh [(size_t)ND * ND];   // fp16(W)
__device__ __half g_ah [(size_t)ND * ND];   // fp16(sigmoid(alpha)) (general path)
__device__ float  g_yslow[(size_t)ND * ND];
__device__ float  g_inv[ND];
__device__ float  g_rowsum[ND];             // ||x||^2 / (||x|| + 1e-8) per row
__device__ int    g_flags[NTILES];          // y_slow tile-ready flags
__device__ int    g_mismatch;               // 0 -> alpha elementwise-constant
__device__ float  g_sigc;                   // sigmoid(alpha[0])

// ---------------- small helpers ---------------------------------------------
__device__ __forceinline__ uint32_t smem_u32_of(const void* p) {
    uint32_t a;
    asm("{ .reg .u64 t; cvta.to.shared.u64 t, %1; cvt.u32.u64 %0, t; }"
        : "=r"(a) : "l"(p));
    return a;
}

__device__ __forceinline__ void cp16(uint32_t dst, const void* src) {
    asm volatile("cp.async.cg.shared.global [%0], [%1], 16;" :: "r"(dst), "l"(src));
}

__device__ __forceinline__ void ldsm_x4(uint32_t r[4], uint32_t addr) {
    asm volatile("ldmatrix.sync.aligned.m8n8.x4.shared.b16 {%0,%1,%2,%3}, [%4];"
                 : "=r"(r[0]), "=r"(r[1]), "=r"(r[2]), "=r"(r[3]) : "r"(addr));
}

__device__ __forceinline__ void mma16816(float c[4], const uint32_t a[4],
                                         uint32_t b0, uint32_t b1) {
    asm volatile(
        "mma.sync.aligned.m16n8k16.row.col.f32.f16.f16.f32 "
        "{%0,%1,%2,%3}, {%4,%5,%6,%7}, {%8,%9}, {%0,%1,%2,%3};"
        : "+f"(c[0]), "+f"(c[1]), "+f"(c[2]), "+f"(c[3])
        : "r"(a[0]), "r"(a[1]), "r"(a[2]), "r"(a[3]), "r"(b0), "r"(b1));
}

// accurate cheap tanh: 1 - 2/(e^{2y}+1), MUFU ex2 + rcp (err ~1e-6)
__device__ __forceinline__ float fast_tanh(float y) {
    float e = __expf(2.0f * y);
    return 1.0f - __fdividef(2.0f, e + 1.0f);
}

// ---------------- prep kernels -----------------------------------------------
// rownorm + alpha-constancy scan. grid = ND blocks x 256 threads.
// Each block: row-sum of x[row,:] AND scans a 4096-element slice of alpha.
__global__ void rownorm_kernel(const float* __restrict__ x,
                               const float* __restrict__ alpha) {
    const int row = blockIdx.x;
    const float4* xr = (const float4*)(x + (size_t)row * ND);
    float s = 0.f;
    for (int i = threadIdx.x; i < ND / 4; i += blockDim.x) {
        float4 v = xr[i];
        s += v.x * v.x + v.y * v.y + v.z * v.z + v.w * v.w;
    }
    // alpha slice scan: block b covers float4 indices [b*1024, (b+1)*1024)
    const float aref = __ldg(&alpha[0]);
    const float4* ar = (const float4*)alpha + (size_t)row * (ND / 4);
    bool diff = false;
    for (int i = threadIdx.x; i < ND / 4; i += blockDim.x) {
        float4 a = ar[i];
        diff |= (a.x != aref) | (a.y != aref) | (a.z != aref) | (a.w != aref);
    }
    if (__syncthreads_or(diff)) {
        if (threadIdx.x == 0) atomicExch(&g_mismatch, 1);
    }
    if (row == 0 && threadIdx.x == 0)
        g_sigc = __fdividef(1.f, 1.f + __expf(-aref));

    for (int o = 16; o; o >>= 1) s += __shfl_down_sync(0xFFFFFFFFu, s, o);
    __shared__ float red[8];
    if ((threadIdx.x & 31) == 0) red[threadIdx.x >> 5] = s;
    __syncthreads();
    if (threadIdx.x < 8) {
        float t = red[threadIdx.x];
        for (int o = 4; o; o >>= 1) t += __shfl_down_sync(0xFFu, t, o);
        if (threadIdx.x == 0) {
            float inv = 1.f / (sqrtf(t) + 1e-8f);
            g_inv[row] = inv;
            g_rowsum[row] = t * inv;   // sum_j x_norm[b,j]*x[b,j], exact fp32
        }
    }
}

// 2 float4 per thread; produces xh always, xxh only on the general path
__global__ void prep_x_kernel(const float* __restrict__ x) {
    const size_t base = 2 * ((size_t)blockIdx.x * blockDim.x + threadIdx.x);
    const int need_xx = g_mismatch;        // set by rownorm (stream-serial)
    float4 v0 = ((const float4*)x)[base];
    float4 v1 = ((const float4*)x)[base + 1];
    const float inv0 = g_inv[base >> 10];
    const float inv1 = g_inv[(base + 1) >> 10];
#pragma unroll
    for (int j = 0; j < 2; j++) {
        float4 v = j ? v1 : v0;
        float inv = j ? inv1 : inv0;
        size_t i = base + j;
        ((__half2*)g_xh)[2 * i + 0]  = __floats2half2_rn(v.x, v.y);
        ((__half2*)g_xh)[2 * i + 1]  = __floats2half2_rn(v.z, v.w);
        if (need_xx) {
            ((__half2*)g_xxh)[2 * i + 0] = __floats2half2_rn(v.x * v.x * inv, v.y * v.y * inv);
            ((__half2*)g_xxh)[2 * i + 1] = __floats2half2_rn(v.z * v.z * inv, v.w * v.w * inv);
        }
    }
}

// W prep always; alpha read/sigmoid/ah write only on the general path
__global__ void prep_wa_kernel(const float* __restrict__ W,
                               const float* __restrict__ alpha) {
    const size_t base = 2 * ((size_t)blockIdx.x * blockDim.x + threadIdx.x);
    const int need_a = g_mismatch;         // set by rownorm (stream-serial)
    float4 w0 = ((const float4*)W)[base];
    float4 w1 = ((const float4*)W)[base + 1];
    ((__half2*)g_wh)[2 * base + 0] = __floats2half2_rn(w0.x, w0.y);
    ((__half2*)g_wh)[2 * base + 1] = __floats2half2_rn(w0.z, w0.w);
    ((__half2*)g_wh)[2 * base + 2] = __floats2half2_rn(w1.x, w1.y);
    ((__half2*)g_wh)[2 * base + 3] = __floats2half2_rn(w1.z, w1.w);
    if (need_a) {
        float4 a0 = ((const float4*)alpha)[base];
        float4 a1 = ((const float4*)alpha)[base + 1];
#pragma unroll
        for (int j = 0; j < 2; j++) {
            float4 a = j ? a1 : a0;
            size_t i = base + j;
            float s0 = __fdividef(1.f, 1.f + __expf(-a.x));
            float s1 = __fdividef(1.f, 1.f + __expf(-a.y));
            float s2 = __fdividef(1.f, 1.f + __expf(-a.z));
            float s3 = __fdividef(1.f, 1.f + __expf(-a.w));
            ((__half2*)g_ah)[2 * i + 0] = __floats2half2_rn(s0, s1);
            ((__half2*)g_ah)[2 * i + 1] = __floats2half2_rn(s2, s3);
        }
    }
}

// ---------------- GEMM -------------------------------------------------------
// load one BK stage of A (BM x BK) and B (BN x BK), SW128 swizzled; 128 threads
__device__ __forceinline__ void load_stage(uint32_t smem_u32, int buf,
                                           const char* gA, const char* gB,
                                           int ks, int tid)
{
    const uint32_t sb = smem_u32 + buf * STAGE_BYTES;
    const size_t kof = (size_t)ks * (BK * 2);        // bytes into K
#pragma unroll
    for (int i = 0; i < 8; i++) {                    // A: 1024 chunks of 16B
        int c = tid + (i << 7);
        int r = c >> 3, kc = (c & 7) << 4;
        uint32_t off = (uint32_t)(r << 7) + kc;
        uint32_t sw = off ^ ((off >> 3) & 0x70);
        cp16(sb + sw, gA + (size_t)r * (ND * 2) + kof + kc);
    }
#pragma unroll
    for (int i = 0; i < 8; i++) {                    // B: 1024 chunks of 16B
        int c = tid + (i << 7);
        int r = c >> 3, kc = (c & 7) << 4;
        uint32_t off = (uint32_t)(r << 7) + kc;
        uint32_t sw = off ^ ((off >> 3) & 0x70);
        cp16(sb + OFF_B + sw, gB + (size_t)r * (ND * 2) + kof + kc);
    }
}

__global__ void __launch_bounds__(128, 2)
gemm_both_kernel(const float* __restrict__ bias, const float* __restrict__ eta_ptr,
                 float* __restrict__ out)
{
    extern __shared__ char smem[];
    const uint32_t smem_u32 = smem_u32_of(smem);
    const int tid = threadIdx.x;
    const int lane = tid & 31;
    const int wid = tid >> 5;             // 4 warps
    const int warp_m = wid & 1;           // 2 x 64 rows
    const int warp_n = wid >> 1;          // 2 x 64 cols

    // which GEMM: first NTILES CTAs -> y_slow, rest -> plastic
    const int mode = (blockIdx.x >= NTILES) ? 1 : 0;
    const int bid = blockIdx.x - mode * NTILES;

    const int aconst = (g_mismatch == 0);   // alpha elementwise-constant?
    if (mode == 1 && aconst) return;        // GEMM2 not needed: rank-1 fast path

    // grouped rasterization: 8 M-tiles per group, N sweeps fastest
    const int num_n = ND / BN;            // 32
    const int GROUP = 8;
    const int group = bid / (GROUP * num_n);
    const int tile_m = group * GROUP + (bid % GROUP);
    const int tile_n = (bid % (GROUP * num_n)) / GROUP;
    const int tile_id = tile_m * num_n + tile_n;

    const char* gA = (const char*)(mode ? g_xxh : g_xh) + (size_t)tile_m * BM * (ND * 2);
    const char* gB = (const char*)(mode ? g_ah  : g_wh) + (size_t)tile_n * BN * (ND * 2);

    // per-thread ldmatrix address components
    uint32_t a_row[4], a_xor[4];
#pragma unroll
    for (int mt = 0; mt < 4; mt++) {
        int r = warp_m * 64 + mt * 16 + (lane & 15);
        a_row[mt] = (uint32_t)(r << 7);
        a_xor[mt] = (uint32_t)((r & 7) << 4);
    }
    const uint32_t a_half = (uint32_t)((lane >> 4) << 4);
    uint32_t b_row[4], b_xor[4];
#pragma unroll
    for (int p = 0; p < 4; p++) {
        int r = warp_n * 64 + p * 16 + ((lane >> 4) << 3) + (lane & 7);
        b_row[p] = (uint32_t)(r << 7);
        b_xor[p] = (uint32_t)((r & 7) << 4);
    }
    const uint32_t b_half = (uint32_t)(((lane >> 3) & 1) << 4);

    float c[4][8][4];
#pragma unroll
    for (int i = 0; i < 4; i++)
#pragma unroll
        for (int j = 0; j < 8; j++)
#pragma unroll
            for (int k = 0; k < 4; k++) c[i][j][k] = 0.f;

    // double-buffered operand fragments
    uint32_t af[2][4][4];
    uint32_t bf[2][8][2];

    load_stage(smem_u32, 0, gA, gB, 0, tid);
    asm volatile("cp.async.commit_group;" ::: "memory");
    load_stage(smem_u32, 1, gA, gB, 1, tid);
    asm volatile("cp.async.commit_group;" ::: "memory");

    int buf = 0;
    int cur = 0;
#pragma unroll 1
    for (int s = 0; s < KTILES; s++) {
        if (s < KTILES - 2) asm volatile("cp.async.wait_group 1;" ::: "memory");
        else                asm volatile("cp.async.wait_group 0;" ::: "memory");
        __syncthreads();

        const uint32_t sbA = smem_u32 + buf * STAGE_BYTES;
        const uint32_t sbB = sbA + OFF_B;

        // fragments for kk = 0 (R14 ordering: before next-stage cp.async)
        {
            const uint32_t kb = 0;
#pragma unroll
            for (int mt = 0; mt < 4; mt++)
                ldsm_x4(af[cur][mt], sbA + a_row[mt] + ((kb + a_half) ^ a_xor[mt]));
#pragma unroll
            for (int p = 0; p < 4; p++) {
                uint32_t r[4];
                ldsm_x4(r, sbB + b_row[p] + ((kb + b_half) ^ b_xor[p]));
                bf[cur][2 * p][0] = r[0]; bf[cur][2 * p][1] = r[1];
                bf[cur][2 * p + 1][0] = r[2]; bf[cur][2 * p + 1][1] = r[3];
            }
        }

        if (s + 2 < KTILES) {
            int nbuf = buf + 2; if (nbuf >= STAGES) nbuf -= STAGES;
            load_stage(smem_u32, nbuf, gA, gB, s + 2, tid);
            asm volatile("cp.async.commit_group;" ::: "memory");
        }

#pragma unroll
        for (int kk = 0; kk < 4; kk++) {
            const int nxt = cur ^ 1;
            if (kk < 3) {
                const uint32_t kb = (uint32_t)((kk + 1) << 5);
#pragma unroll
                for (int mt = 0; mt < 4; mt++)
                    ldsm_x4(af[nxt][mt], sbA + a_row[mt] + ((kb + a_half) ^ a_xor[mt]));
#pragma unroll
                for (int p = 0; p < 4; p++) {
                    uint32_t r[4];
                    ldsm_x4(r, sbB + b_row[p] + ((kb + b_half) ^ b_xor[p]));
                    bf[nxt][2 * p][0] = r[0]; bf[nxt][2 * p][1] = r[1];
                    bf[nxt][2 * p + 1][0] = r[2]; bf[nxt][2 * p + 1][1] = r[3];
                }
            }
#pragma unroll
            for (int mt = 0; mt < 4; mt++)
#pragma unroll
                for (int nt = 0; nt < 8; nt++)
                    mma16816(c[mt][nt], af[cur][mt], bf[cur][nt][0], bf[cur][nt][1]);
            if (kk < 3) cur = nxt;
        }
        buf++; if (buf >= STAGES) buf = 0;
    }

    // ---------------- epilogue ----------------
    const int row0 = tile_m * BM + warp_m * 64 + (lane >> 2);
    const int col0 = tile_n * BN + warp_n * 64 + ((lane & 3) << 1);

    if (mode == 0) {
        if (aconst) {
            // rank-1 fast path: out = y + eta*tanh(y)*(sigc*rowsum[row]), exact fp32 s
            const float eta = *eta_ptr;
            const float sigc = g_sigc;
#pragma unroll
            for (int mt = 0; mt < 4; mt++) {
                const int r0 = row0 + mt * 16;
                const int r1 = r0 + 8;
                const float s0 = sigc * __ldg(&g_rowsum[r0]);
                const float s1 = sigc * __ldg(&g_rowsum[r1]);
#pragma unroll
                for (int nt = 0; nt < 8; nt++) {
                    const int col = col0 + nt * 8;
                    float b0 = __ldg(&bias[col]);
                    float b1 = __ldg(&bias[col + 1]);
                    float y00 = c[mt][nt][0] + b0, y01 = c[mt][nt][1] + b1;
                    float y10 = c[mt][nt][2] + b0, y11 = c[mt][nt][3] + b1;
                    float2 v0, v1;
                    v0.x = y00 + eta * fast_tanh(y00) * s0;
                    v0.y = y01 + eta * fast_tanh(y01) * s0;
                    v1.x = y10 + eta * fast_tanh(y10) * s1;
                    v1.y = y11 + eta * fast_tanh(y11) * s1;
                    *(float2*)&out[(size_t)r0 * ND + col] = v0;
                    *(float2*)&out[(size_t)r1 * ND + col] = v1;
                }
            }
        } else {
            // general path: write y_slow tile, then release its flag
#pragma unroll
            for (int mt = 0; mt < 4; mt++) {
#pragma unroll
                for (int nt = 0; nt < 8; nt++) {
                    const int col = col0 + nt * 8;
                    const int r0 = row0 + mt * 16;
                    const int r1 = r0 + 8;
                    float b0 = __ldg(&bias[col]);
                    float b1 = __ldg(&bias[col + 1]);
                    float2 v0 = make_float2(c[mt][nt][0] + b0, c[mt][nt][1] + b1);
                    float2 v1 = make_float2(c[mt][nt][2] + b0, c[mt][nt][3] + b1);
                    *(float2*)&g_yslow[(size_t)r0 * ND + col] = v0;
                    *(float2*)&g_yslow[(size_t)r1 * ND + col] = v1;
                }
            }
            __threadfence();
            __syncthreads();
            if (tid == 0) atomicExch(&g_flags[tile_id], 1);
        }
    } else {
        // general path GEMM2: wait for matching y_slow tile
        if (tid == 0) {
            while (atomicCAS(&g_flags[tile_id], 1, 1) == 0) { }
        }
        __syncthreads();
        __threadfence();
        const float eta = *eta_ptr;
#pragma unroll
        for (int mt = 0; mt < 4; mt++) {
#pragma unroll
            for (int nt = 0; nt < 8; nt++) {
                const int col = col0 + nt * 8;
                const int r0 = row0 + mt * 16;
                const int r1 = r0 + 8;
                float2 y0 = *(const float2*)&g_yslow[(size_t)r0 * ND + col];
                float2 y1 = *(const float2*)&g_yslow[(size_t)r1 * ND + col];
                float2 v0, v1;
                v0.x = y0.x + eta * fast_tanh(y0.x) * c[mt][nt][0];
                v0.y = y0.y + eta * fast_tanh(y0.y) * c[mt][nt][1];
                v1.x = y1.x + eta * fast_tanh(y1.x) * c[mt][nt][2];
                v1.y = y1.y + eta * fast_tanh(y1.y) * c[mt][nt][3];
                *(float2*)&out[(size_t)r0 * ND + col] = v0;
                *(float2*)&out[(size_t)r1 * ND + col] = v1;
            }
        }
    }
}

// ---------------- launch -----------------------------------------------------
extern "C" void kernel_launch(void* const* d_in, const int* in_sizes, int n_in,
                              void* d_out, int out_size)
{
    // metadata order: x, W, alpha, eta, bias — resolve defensively by size
    const float* big[3] = {nullptr, nullptr, nullptr};
    const float* eta = nullptr;
    const float* bias = nullptr;
    int nb = 0;
    for (int i = 0; i < n_in; i++) {
        if (in_sizes[i] == 1) eta = (const float*)d_in[i];
        else if (in_sizes[i] == ND) bias = (const float*)d_in[i];
        else if (nb < 3) big[nb++] = (const float*)d_in[i];
    }
    const float* x = big[0];
    const float* W = big[1];
    const float* alpha = big[2];
    float* out = (float*)d_out;

    cudaFuncSetAttribute(gemm_both_kernel, cudaFuncAttributeMaxDynamicSharedMemorySize,
                         SMEM_BYTES);

    // reset flags + mismatch (graph-capturable memsets)
    void* flags_ptr = nullptr;
    cudaGetSymbolAddress(&flags_ptr, g_flags);
    cudaMemsetAsync(flags_ptr, 0, NTILES * sizeof(int));
    void* mm_ptr = nullptr;
    cudaGetSymbolAddress(&mm_ptr, g_mismatch);
    cudaMemsetAsync(mm_ptr, 0, sizeof(int));

    rownorm_kernel<<<ND, 256>>>(x, alpha);               // also detects alpha const
    const int n8blocks = (ND * (ND / 4)) / (256 * 2);    // 8192
    prep_x_kernel<<<n8blocks, 256>>>(x);
    prep_wa_kernel<<<n8blocks, 256>>>(W, alpha);

    gemm_both_kernel<<<2 * NTILES, 128, SMEM_BYTES>>>(bias, eta, out);
}